// round 9
// baseline (speedup 1.0000x reference)
#include <cuda_runtime.h>
#include <math.h>

#define Nn  32768
#define Cc  512
#define Aa  64
#define CIi 1024
#define QD  576          // C + A
#define EPSf 1e-7f

// ---------------- scratch: ONE contiguous struct so a single memset zeroes it ----
struct Acc {
    float q[QD];      // W_query@h partials (bias added later)
    float er[Cc];     // W_erase@h partials
    float t1[Cc];     // Wch@h partials
    float t2[Cc];     // Wci@x partials
    float s1[QD];     // sum_i e_i * full_mem[i,j]
    float s2[Cc];     // sum_i e_i^2 * mem[i,c]
    float scal[16];   // 1:us.h 2:ul.h 3:uca[:N].h 6:uca[N:].x 7:E 8:S
    unsigned cnt;     // last-block-done counter
};
__device__ Acc g;

// ---------------- K1: all matvecs + small dots (column-chunked, 868 blocks) ------
__global__ __launch_bounds__(256) void k_matvec(
    const float* __restrict__ h,  const float* __restrict__ x,
    const float* __restrict__ Wq, const float* __restrict__ We,
    const float* __restrict__ Wch, const float* __restrict__ Wci,
    const float* __restrict__ us, const float* __restrict__ ul,
    const float* __restrict__ uca)
{
    int b = blockIdx.x, t = threadIdx.x;
    int w = t >> 5, lane = t & 31;

    if (b < 800) {
        const float* W; float* out; int row0, chunk;
        if (b < 288)      { W = Wq;  out = g.q;  row0 = (b >> 2) * 8;        chunk = b & 3; }
        else if (b < 544) { int bb = b - 288; W = We;  out = g.er; row0 = (bb >> 2) * 8; chunk = bb & 3; }
        else              { int bb = b - 544; W = Wch; out = g.t1; row0 = (bb >> 2) * 8; chunk = bb & 3; }

        const float4* v4 = (const float4*)h + chunk * 2048;
        const size_t cbase = (size_t)chunk * 8192;

        float acc[8];
        #pragma unroll
        for (int r = 0; r < 8; r++) acc[r] = 0.f;

        #pragma unroll 2
        for (int i = t; i < 2048; i += 256) {
            float4 hv = v4[i];
            #pragma unroll
            for (int r = 0; r < 8; r++) {
                float4 wv = reinterpret_cast<const float4*>(W + (size_t)(row0 + r) * Nn + cbase)[i];
                acc[r] += wv.x * hv.x + wv.y * hv.y + wv.z * hv.z + wv.w * hv.w;
            }
        }
        #pragma unroll
        for (int r = 0; r < 8; r++)
            for (int o = 16; o; o >>= 1) acc[r] += __shfl_xor_sync(0xffffffffu, acc[r], o);

        __shared__ float sm[8][8];
        if (lane == 0) {
            #pragma unroll
            for (int r = 0; r < 8; r++) sm[w][r] = acc[r];
        }
        __syncthreads();
        if (t < 8) {
            float v = 0.f;
            #pragma unroll
            for (int w2 = 0; w2 < 8; w2++) v += sm[w2][t];
            atomicAdd(&out[row0 + t], v);
        }
    } else if (b < 864) {
        int row0 = (b - 800) * 8;
        const float4* v4 = (const float4*)x;
        float acc[8];
        #pragma unroll
        for (int r = 0; r < 8; r++) acc[r] = 0.f;
        {
            int i = t;
            float4 hv = v4[i];
            #pragma unroll
            for (int r = 0; r < 8; r++) {
                float4 wv = reinterpret_cast<const float4*>(Wci + (size_t)(row0 + r) * CIi)[i];
                acc[r] += wv.x * hv.x + wv.y * hv.y + wv.z * hv.z + wv.w * hv.w;
            }
        }
        #pragma unroll
        for (int r = 0; r < 8; r++)
            for (int o = 16; o; o >>= 1) acc[r] += __shfl_xor_sync(0xffffffffu, acc[r], o);
        __shared__ float sm2[8][8];
        if (lane == 0) {
            #pragma unroll
            for (int r = 0; r < 8; r++) sm2[w][r] = acc[r];
        }
        __syncthreads();
        if (t < 8) {
            float v = 0.f;
            #pragma unroll
            for (int w2 = 0; w2 < 8; w2++) v += sm2[w2][t];
            g.t2[row0 + t] = v;
        }
    } else {
        int d = b - 864;
        const float* u; const float* vec; int L; int slot;
        if (d == 0)      { u = us;       vec = h; L = Nn;  slot = 1; }
        else if (d == 1) { u = ul;       vec = h; L = Nn;  slot = 2; }
        else if (d == 2) { u = uca;      vec = h; L = Nn;  slot = 3; }
        else             { u = uca + Nn; vec = x; L = CIi; slot = 6; }
        float acc = 0.f;
        const float4* u4 = (const float4*)u;
        const float4* v4 = (const float4*)vec;
        for (int i = t; i < (L >> 2); i += 256) {
            float4 a = u4[i], c = v4[i];
            acc += a.x * c.x + a.y * c.y + a.z * c.z + a.w * c.w;
        }
        for (int o = 16; o; o >>= 1) acc += __shfl_xor_sync(0xffffffffu, acc, o);
        __shared__ float sd[8];
        if (lane == 0) sd[w] = acc;
        __syncthreads();
        if (t == 0) {
            float tot = 0.f;
            #pragma unroll
            for (int k = 0; k < 8; k++) tot += sd[k];
            g.scal[slot] = tot;
        }
    }
}

// ---------------- K2: FUSED single pass over full_mem -----------------------------
// z_i is bounded (|z| <~ 8 for this operator: beta<=~7, |cos|<=1, gamma<1,
// |ema|<~0.5) so exp needs no max-shift -> softmax weighting fused with the
// similarity pass. Each warp: dot+norm via butterfly (all lanes get the total),
// e = exp(z) immediately, accumulate e*row / e^2*row from registers.
// Last block (atomic counter) performs the final combine and writes the output.
__global__ __launch_bounds__(256, 2) void k_main(
    const float* __restrict__ Amat, const float* __restrict__ M,
    const float* __restrict__ ema, const float* __restrict__ bq,
    const float* __restrict__ bsh, const float* __restrict__ blru,
    const float* __restrict__ be,  const float* __restrict__ bca,
    float* __restrict__ out)
{
    __shared__ float qs[QD];
    __shared__ float s1sh[QD];
    __shared__ float s2sh[Cc];
    __shared__ float red[8];
    __shared__ float sc[2];
    __shared__ float es[2];
    __shared__ unsigned lastf;
    int t = threadIdx.x, w = t >> 5, lane = t & 31;

    // prolog: q+bias -> shared, ||q||, beta, gamma (redundant per block, cheap)
    float p = 0.f;
    for (int j = t; j < QD; j += 256) {
        float v = g.q[j] + bq[j];
        qs[j] = v;
        p += v * v;
        s1sh[j] = 0.f;
    }
    for (int j = t; j < Cc; j += 256) s2sh[j] = 0.f;
    for (int o = 16; o; o >>= 1) p += __shfl_xor_sync(0xffffffffu, p, o);
    if (lane == 0) red[w] = p;
    __syncthreads();
    if (t == 0) {
        float qs2 = 0.f;
        #pragma unroll
        for (int k = 0; k < 8; k++) qs2 += red[k];
        float qn = fmaxf(sqrtf(qs2), EPSf);
        float bp = g.scal[1] + bsh[0];
        float beta = ((bp > 20.f) ? bp : log1pf(__expf(bp))) + 1.f;
        float gp = g.scal[2] + blru[0];
        sc[0] = beta / qn;
        sc[1] = 1.f / (1.f + __expf(-gp));
        es[0] = 0.f; es[1] = 0.f;
    }
    __syncthreads();
    float betap = sc[0], gamma = sc[1];

    int gw = blockIdx.x * 8 + w;                 // 8192 warps, 4 rows each
    float a1x = 0.f, a1y = 0.f;
    float4 c1[4], c2[4];
    #pragma unroll
    for (int k = 0; k < 4; k++) {
        c1[k] = make_float4(0.f, 0.f, 0.f, 0.f);
        c2[k] = make_float4(0.f, 0.f, 0.f, 0.f);
    }
    float eacc = 0.f, sacc = 0.f;

    float q0a = qs[2 * lane], q1a = qs[2 * lane + 1];

    #pragma unroll
    for (int rr = 0; rr < 4; rr += 2) {          // 2-row interleave for MLP
        int row0 = gw * 4 + rr;
        float2 av0 = ((const float2*)(Amat + (size_t)row0 * Aa))[lane];
        float2 av1 = ((const float2*)(Amat + (size_t)(row0 + 1) * Aa))[lane];
        float4 v0[4], v1[4];
        const float4* c0p = (const float4*)(M + (size_t)row0 * Cc);
        const float4* c1p = (const float4*)(M + (size_t)(row0 + 1) * Cc);
        #pragma unroll
        for (int k = 0; k < 4; k++) {
            v0[k] = c0p[lane + 32 * k];
            v1[k] = c1p[lane + 32 * k];
        }
        float d0 = av0.x * q0a + av0.y * q1a;
        float s0 = av0.x * av0.x + av0.y * av0.y;
        float d1 = av1.x * q0a + av1.y * q1a;
        float s1 = av1.x * av1.x + av1.y * av1.y;
        #pragma unroll
        for (int k = 0; k < 4; k++) {
            int cb = Aa + 4 * (lane + 32 * k);
            float qa = qs[cb], qb = qs[cb + 1], qc = qs[cb + 2], qd = qs[cb + 3];
            d0 += v0[k].x * qa + v0[k].y * qb + v0[k].z * qc + v0[k].w * qd;
            s0 += v0[k].x * v0[k].x + v0[k].y * v0[k].y + v0[k].z * v0[k].z + v0[k].w * v0[k].w;
            d1 += v1[k].x * qa + v1[k].y * qb + v1[k].z * qc + v1[k].w * qd;
            s1 += v1[k].x * v1[k].x + v1[k].y * v1[k].y + v1[k].z * v1[k].z + v1[k].w * v1[k].w;
        }
        #pragma unroll
        for (int o = 16; o; o >>= 1) {
            d0 += __shfl_xor_sync(0xffffffffu, d0, o);
            d1 += __shfl_xor_sync(0xffffffffu, d1, o);
            s0 += __shfl_xor_sync(0xffffffffu, s0, o);
            s1 += __shfl_xor_sync(0xffffffffu, s1, o);
        }
        // all lanes hold the totals after butterfly
        float z0 = betap * d0 / fmaxf(sqrtf(s0), EPSf) - gamma * __ldg(&ema[row0]);
        float z1 = betap * d1 / fmaxf(sqrtf(s1), EPSf) - gamma * __ldg(&ema[row0 + 1]);
        float e0 = __expf(z0), e1 = __expf(z1);
        float f0 = e0 * e0,   f1 = e1 * e1;

        a1x += e0 * av0.x + e1 * av1.x;
        a1y += e0 * av0.y + e1 * av1.y;
        #pragma unroll
        for (int k = 0; k < 4; k++) {
            c1[k].x += e0 * v0[k].x + e1 * v1[k].x;
            c1[k].y += e0 * v0[k].y + e1 * v1[k].y;
            c1[k].z += e0 * v0[k].z + e1 * v1[k].z;
            c1[k].w += e0 * v0[k].w + e1 * v1[k].w;
            c2[k].x += f0 * v0[k].x + f1 * v1[k].x;
            c2[k].y += f0 * v0[k].y + f1 * v1[k].y;
            c2[k].z += f0 * v0[k].z + f1 * v1[k].z;
            c2[k].w += f0 * v0[k].w + f1 * v1[k].w;
        }
        if (lane == 0) { eacc += e0 + e1; sacc += f0 + f1; }
    }

    // block-level combine (fixed per-lane column ownership -> no smem conflicts)
    atomicAdd(&s1sh[2 * lane],     a1x);
    atomicAdd(&s1sh[2 * lane + 1], a1y);
    #pragma unroll
    for (int k = 0; k < 4; k++) {
        int base = 4 * (lane + 32 * k);
        atomicAdd(&s1sh[Aa + base + 0], c1[k].x);
        atomicAdd(&s1sh[Aa + base + 1], c1[k].y);
        atomicAdd(&s1sh[Aa + base + 2], c1[k].z);
        atomicAdd(&s1sh[Aa + base + 3], c1[k].w);
        atomicAdd(&s2sh[base + 0], c2[k].x);
        atomicAdd(&s2sh[base + 1], c2[k].y);
        atomicAdd(&s2sh[base + 2], c2[k].z);
        atomicAdd(&s2sh[base + 3], c2[k].w);
    }
    if (lane == 0) { atomicAdd(&es[0], eacc); atomicAdd(&es[1], sacc); }
    __syncthreads();

    // global combine
    for (int j = t; j < QD; j += 256) atomicAdd(&g.s1[j], s1sh[j]);
    for (int j = t; j < Cc; j += 256) atomicAdd(&g.s2[j], s2sh[j]);
    if (t == 0) { atomicAdd(&g.scal[7], es[0]); atomicAdd(&g.scal[8], es[1]); }

    // last-block-done: final combine + output write
    __threadfence();
    if (t == 0) {
        unsigned old = atomicAdd(&g.cnt, 1u);
        lastf = (old == gridDim.x - 1) ? 1u : 0u;
    }
    __syncthreads();
    if (lastf) {
        __threadfence();
        float E = __ldcg(&g.scal[7]);
        float S = __ldcg(&g.scal[8]);
        float invE = 1.f / E;
        float inv2 = invE * invE;
        float alpha = g.scal[3] + g.scal[6] + bca[0];
        for (int j = t; j < QD; j += 256) {
            float s1v = __ldcg(&g.s1[j]);
            if (j < Aa) {
                out[j] = s1v * invE;
            } else {
                int c = j - Aa;
                float cand = fmaxf(g.t1[c] + alpha * g.t2[c], 0.f);
                float erv  = g.er[c] + be[c];
                out[j] = s1v * invE - erv * (__ldcg(&g.s2[c]) * inv2) + cand * (S * inv2);
            }
        }
    }
}

extern "C" void kernel_launch(void* const* d_in, const int* in_sizes, int n_in,
                              void* d_out, int out_size)
{
    const float* h    = (const float*)d_in[0];
    const float* x    = (const float*)d_in[1];
    const float* mem  = (const float*)d_in[2];
    const float* amat = (const float*)d_in[3];
    const float* ema  = (const float*)d_in[4];
    const float* Wq   = (const float*)d_in[5];
    const float* bq   = (const float*)d_in[6];
    const float* us   = (const float*)d_in[7];
    const float* bsh  = (const float*)d_in[8];
    const float* ul   = (const float*)d_in[9];
    const float* blru = (const float*)d_in[10];
    const float* We   = (const float*)d_in[11];
    const float* be   = (const float*)d_in[12];
    const float* Wch  = (const float*)d_in[13];
    const float* Wci  = (const float*)d_in[14];
    const float* uca  = (const float*)d_in[15];
    const float* bca  = (const float*)d_in[16];

    void* accp = nullptr;
    cudaGetSymbolAddress(&accp, g);
    cudaMemsetAsync(accp, 0, sizeof(Acc));

    k_matvec<<<868, 256>>>(h, x, Wq, We, Wch, Wci, us, ul, uca);
    k_main<<<1024, 256>>>(amat, mem, ema, bq, bsh, blru, be, bca, (float*)d_out);
}

// round 10
// speedup vs baseline: 1.1493x; 1.1493x over previous
#include <cuda_runtime.h>
#include <math.h>

#define Nn  32768
#define Cc  512
#define Aa  64
#define CIi 1024
#define QD  576          // C + A
#define EPSf 1e-7f

// ---------------- scratch: ONE contiguous struct so a single memset zeroes it ----
struct Acc {
    float q[QD];      // W_query@h partials (bias added later)
    float er[Cc];     // W_erase@h partials
    float t1[Cc];     // Wch@h partials
    float t2[Cc];     // Wci@x partials
    float s1[QD];     // sum_i e_i * full_mem[i,j]
    float s2[Cc];     // sum_i e_i^2 * mem[i,c]
    float scal[16];   // 1:us.h 2:ul.h 3:uca[:N].h 6:uca[N:].x 7:E 8:S
    unsigned zkey;    // order-preserving encoded max; memset-0 == -inf identity
    unsigned cnt;     // last-block-done counter for pass2 finalize
};
__device__ Acc g;
__device__ float g_z[Nn];

__device__ __forceinline__ unsigned encf(float f) {
    unsigned u = __float_as_uint(f);
    return (u & 0x80000000u) ? ~u : (u | 0x80000000u);
}
__device__ __forceinline__ float decf(unsigned k) {
    return __uint_as_float((k & 0x80000000u) ? (k & 0x7FFFFFFFu) : ~k);
}

// ---------------- K1: all matvecs + small dots (8-way chunked, 1668 blocks) ------
//  b < 576   : W_query (72 groups x 8 chunks)  -> g.q
//  b < 1088  : W_erase (64 groups x 8 chunks)  -> g.er
//  b < 1600  : W_ch    (64 groups x 8 chunks)  -> g.t1
//  b < 1664  : W_ci    (64 groups x 1 chunk)   -> g.t2
//  b < 1668  : dots us.h, ul.h, uca[:N].h, uca[N:].x -> g.scal slots
__global__ __launch_bounds__(256) void k_matvec(
    const float* __restrict__ h,  const float* __restrict__ x,
    const float* __restrict__ Wq, const float* __restrict__ We,
    const float* __restrict__ Wch, const float* __restrict__ Wci,
    const float* __restrict__ us, const float* __restrict__ ul,
    const float* __restrict__ uca)
{
    int b = blockIdx.x, t = threadIdx.x;
    int w = t >> 5, lane = t & 31;

    if (b < 1600) {
        const float* W; float* out; int row0, chunk;
        if (b < 576)       { W = Wq;  out = g.q;  row0 = (b >> 3) * 8;  chunk = b & 7; }
        else if (b < 1088) { int bb = b - 576;  W = We;  out = g.er; row0 = (bb >> 3) * 8; chunk = bb & 7; }
        else               { int bb = b - 1088; W = Wch; out = g.t1; row0 = (bb >> 3) * 8; chunk = bb & 7; }

        const float4* v4 = (const float4*)h + chunk * 1024;   // 4096 floats / chunk
        const size_t cbase = (size_t)chunk * 4096;

        float acc[8];
        #pragma unroll
        for (int r = 0; r < 8; r++) acc[r] = 0.f;

        #pragma unroll 2
        for (int i = t; i < 1024; i += 256) {
            float4 hv = v4[i];
            #pragma unroll
            for (int r = 0; r < 8; r++) {
                float4 wv = reinterpret_cast<const float4*>(W + (size_t)(row0 + r) * Nn + cbase)[i];
                acc[r] += wv.x * hv.x + wv.y * hv.y + wv.z * hv.z + wv.w * hv.w;
            }
        }
        #pragma unroll
        for (int r = 0; r < 8; r++)
            for (int o = 16; o; o >>= 1) acc[r] += __shfl_xor_sync(0xffffffffu, acc[r], o);

        __shared__ float sm[8][8];
        if (lane == 0) {
            #pragma unroll
            for (int r = 0; r < 8; r++) sm[w][r] = acc[r];
        }
        __syncthreads();
        if (t < 8) {
            float v = 0.f;
            #pragma unroll
            for (int w2 = 0; w2 < 8; w2++) v += sm[w2][t];
            atomicAdd(&out[row0 + t], v);
        }
    } else if (b < 1664) {
        // W_ci: 8 rows x 1024, one block per group (exclusive rows -> plain store)
        int row0 = (b - 1600) * 8;
        const float4* v4 = (const float4*)x;
        float acc[8];
        #pragma unroll
        for (int r = 0; r < 8; r++) acc[r] = 0.f;
        {
            int i = t;   // 1024/4 = 256 float4 -> exactly one per thread
            float4 hv = v4[i];
            #pragma unroll
            for (int r = 0; r < 8; r++) {
                float4 wv = reinterpret_cast<const float4*>(Wci + (size_t)(row0 + r) * CIi)[i];
                acc[r] += wv.x * hv.x + wv.y * hv.y + wv.z * hv.z + wv.w * hv.w;
            }
        }
        #pragma unroll
        for (int r = 0; r < 8; r++)
            for (int o = 16; o; o >>= 1) acc[r] += __shfl_xor_sync(0xffffffffu, acc[r], o);
        __shared__ float sm2[8][8];
        if (lane == 0) {
            #pragma unroll
            for (int r = 0; r < 8; r++) sm2[w][r] = acc[r];
        }
        __syncthreads();
        if (t < 8) {
            float v = 0.f;
            #pragma unroll
            for (int w2 = 0; w2 < 8; w2++) v += sm2[w2][t];
            g.t2[row0 + t] = v;
        }
    } else {
        int d = b - 1664;
        const float* u; const float* vec; int L; int slot;
        if (d == 0)      { u = us;       vec = h; L = Nn;  slot = 1; }
        else if (d == 1) { u = ul;       vec = h; L = Nn;  slot = 2; }
        else if (d == 2) { u = uca;      vec = h; L = Nn;  slot = 3; }
        else             { u = uca + Nn; vec = x; L = CIi; slot = 6; }
        float acc = 0.f;
        const float4* u4 = (const float4*)u;
        const float4* v4 = (const float4*)vec;
        for (int i = t; i < (L >> 2); i += 256) {
            float4 a = u4[i], c = v4[i];
            acc += a.x * c.x + a.y * c.y + a.z * c.z + a.w * c.w;
        }
        for (int o = 16; o; o >>= 1) acc += __shfl_xor_sync(0xffffffffu, acc, o);
        __shared__ float sd[8];
        if (lane == 0) sd[w] = acc;
        __syncthreads();
        if (t == 0) {
            float tot = 0.f;
            #pragma unroll
            for (int k = 0; k < 8; k++) tot += sd[k];
            g.scal[slot] = tot;
        }
    }
}

// ---------------- K2: pass 1 over full_mem -> z[i], global max -------------------
__global__ __launch_bounds__(256) void k_pass1(
    const float* __restrict__ Amat, const float* __restrict__ M,
    const float* __restrict__ ema, const float* __restrict__ bq,
    const float* __restrict__ bsh, const float* __restrict__ blru)
{
    __shared__ float qs[QD];
    __shared__ float red[8];
    __shared__ float sc[2];
    int t = threadIdx.x, w = t >> 5, lane = t & 31;

    float p = 0.f;
    for (int j = t; j < QD; j += 256) {
        float v = g.q[j] + bq[j];
        qs[j] = v;
        p += v * v;
    }
    for (int o = 16; o; o >>= 1) p += __shfl_xor_sync(0xffffffffu, p, o);
    if (lane == 0) red[w] = p;
    __syncthreads();
    if (t == 0) {
        float qs2 = 0.f;
        #pragma unroll
        for (int k = 0; k < 8; k++) qs2 += red[k];
        float qn = fmaxf(sqrtf(qs2), EPSf);
        float bp = g.scal[1] + bsh[0];
        float beta = ((bp > 20.f) ? bp : log1pf(__expf(bp))) + 1.f;
        float gp = g.scal[2] + blru[0];
        sc[0] = beta / qn;                       // fold 1/||q|| into beta
        sc[1] = 1.f / (1.f + __expf(-gp));       // gamma
    }
    __syncthreads();
    float betap = sc[0], gamma = sc[1];

    int gw = blockIdx.x * 8 + w;                 // 8192 warps, 4 rows each
    float lmax = -3.4e38f;
    #pragma unroll
    for (int rr = 0; rr < 4; rr += 2) {          // 2-row interleave: 2x MLP
        int row0 = gw * 4 + rr;
        float2 av0 = ((const float2*)(Amat + (size_t)row0 * Aa))[lane];
        float2 av1 = ((const float2*)(Amat + (size_t)(row0 + 1) * Aa))[lane];
        float q0a = qs[2 * lane], q1a = qs[2 * lane + 1];
        float d0 = av0.x * q0a + av0.y * q1a;
        float s0 = av0.x * av0.x + av0.y * av0.y;
        float d1 = av1.x * q0a + av1.y * q1a;
        float s1 = av1.x * av1.x + av1.y * av1.y;
        const float4* c0 = (const float4*)(M + (size_t)row0 * Cc);
        const float4* c1 = (const float4*)(M + (size_t)(row0 + 1) * Cc);
        #pragma unroll
        for (int k = 0; k < 4; k++) {
            int idx = lane + 32 * k;
            float4 v0 = c0[idx];
            float4 v1 = c1[idx];
            int cb = Aa + 4 * idx;
            float qa = qs[cb], qb = qs[cb + 1], qc = qs[cb + 2], qd = qs[cb + 3];
            d0 += v0.x * qa + v0.y * qb + v0.z * qc + v0.w * qd;
            s0 += v0.x * v0.x + v0.y * v0.y + v0.z * v0.z + v0.w * v0.w;
            d1 += v1.x * qa + v1.y * qb + v1.z * qc + v1.w * qd;
            s1 += v1.x * v1.x + v1.y * v1.y + v1.z * v1.z + v1.w * v1.w;
        }
        #pragma unroll
        for (int o = 16; o; o >>= 1) {
            d0 += __shfl_xor_sync(0xffffffffu, d0, o);
            d1 += __shfl_xor_sync(0xffffffffu, d1, o);
            s0 += __shfl_xor_sync(0xffffffffu, s0, o);
            s1 += __shfl_xor_sync(0xffffffffu, s1, o);
        }
        if (lane == 0) {
            float z0 = betap * d0 / fmaxf(sqrtf(s0), EPSf) - gamma * ema[row0];
            float z1 = betap * d1 / fmaxf(sqrtf(s1), EPSf) - gamma * ema[row0 + 1];
            g_z[row0] = z0;
            g_z[row0 + 1] = z1;
            lmax = fmaxf(lmax, fmaxf(z0, z1));
        }
    }
    if (lane == 0) red[w] = lmax;
    __syncthreads();
    if (t == 0) {
        float m = red[0];
        #pragma unroll
        for (int k = 1; k < 8; k++) m = fmaxf(m, red[k]);
        atomicMax(&g.zkey, encf(m));
    }
}

// ---------------- K3: pass 2 -> s1, s2, E, S; last block writes output -----------
__global__ __launch_bounds__(256) void k_pass2(
    const float* __restrict__ Amat, const float* __restrict__ M,
    const float* __restrict__ be, const float* __restrict__ bca,
    float* __restrict__ out)
{
    __shared__ float s1sh[QD];
    __shared__ float s2sh[Cc];
    __shared__ float es[2];
    __shared__ unsigned lastf;
    int t = threadIdx.x;
    for (int j = t; j < QD; j += 256) s1sh[j] = 0.f;
    for (int j = t; j < Cc; j += 256) s2sh[j] = 0.f;
    if (t == 0) { es[0] = 0.f; es[1] = 0.f; }
    float zmax = decf(g.zkey);
    __syncthreads();

    int w = t >> 5, lane = t & 31;
    int gw = blockIdx.x * 8 + w;                 // 4096 warps, 8 rows each
    float a1x = 0.f, a1y = 0.f;
    float4 c1[4], c2[4];
    #pragma unroll
    for (int k = 0; k < 4; k++) {
        c1[k] = make_float4(0.f, 0.f, 0.f, 0.f);
        c2[k] = make_float4(0.f, 0.f, 0.f, 0.f);
    }
    float eacc = 0.f, sacc = 0.f;

    for (int r = 0; r < 8; r++) {
        int row = gw * 8 + r;
        float e = __expf(g_z[row] - zmax);
        float e2 = e * e;
        float2 av = ((const float2*)(Amat + (size_t)row * Aa))[lane];
        a1x += e * av.x; a1y += e * av.y;
        const float4* c4 = (const float4*)(M + (size_t)row * Cc);
        #pragma unroll
        for (int k = 0; k < 4; k++) {
            float4 v = c4[lane + 32 * k];
            c1[k].x += e * v.x;  c1[k].y += e * v.y;  c1[k].z += e * v.z;  c1[k].w += e * v.w;
            c2[k].x += e2 * v.x; c2[k].y += e2 * v.y; c2[k].z += e2 * v.z; c2[k].w += e2 * v.w;
        }
        if (lane == 0) { eacc += e; sacc += e2; }
    }

    atomicAdd(&s1sh[2 * lane],     a1x);
    atomicAdd(&s1sh[2 * lane + 1], a1y);
    #pragma unroll
    for (int k = 0; k < 4; k++) {
        int base = 4 * (lane + 32 * k);
        atomicAdd(&s1sh[Aa + base + 0], c1[k].x);
        atomicAdd(&s1sh[Aa + base + 1], c1[k].y);
        atomicAdd(&s1sh[Aa + base + 2], c1[k].z);
        atomicAdd(&s1sh[Aa + base + 3], c1[k].w);
        atomicAdd(&s2sh[base + 0], c2[k].x);
        atomicAdd(&s2sh[base + 1], c2[k].y);
        atomicAdd(&s2sh[base + 2], c2[k].z);
        atomicAdd(&s2sh[base + 3], c2[k].w);
    }
    if (lane == 0) { atomicAdd(&es[0], eacc); atomicAdd(&es[1], sacc); }
    __syncthreads();

    for (int j = t; j < QD; j += 256) atomicAdd(&g.s1[j], s1sh[j]);
    for (int j = t; j < Cc; j += 256) atomicAdd(&g.s2[j], s2sh[j]);
    if (t == 0) { atomicAdd(&g.scal[7], es[0]); atomicAdd(&g.scal[8], es[1]); }

    // last-block-done: final combine + output write (replaces k_fin2)
    __threadfence();
    if (t == 0) {
        unsigned old = atomicAdd(&g.cnt, 1u);
        lastf = (old == gridDim.x - 1) ? 1u : 0u;
    }
    __syncthreads();
    if (lastf) {
        __threadfence();
        float E = __ldcg(&g.scal[7]);
        float S = __ldcg(&g.scal[8]);
        float invE = 1.f / E;
        float inv2 = invE * invE;
        float alpha = g.scal[3] + g.scal[6] + bca[0];
        for (int j = t; j < QD; j += 256) {
            float s1v = __ldcg(&g.s1[j]);
            if (j < Aa) {
                out[j] = s1v * invE;
            } else {
                int c = j - Aa;
                float cand = fmaxf(g.t1[c] + alpha * g.t2[c], 0.f);
                float erv  = g.er[c] + be[c];
                out[j] = s1v * invE - erv * (__ldcg(&g.s2[c]) * inv2) + cand * (S * inv2);
            }
        }
    }
}

extern "C" void kernel_launch(void* const* d_in, const int* in_sizes, int n_in,
                              void* d_out, int out_size)
{
    const float* h    = (const float*)d_in[0];
    const float* x    = (const float*)d_in[1];
    const float* mem  = (const float*)d_in[2];
    const float* amat = (const float*)d_in[3];
    const float* ema  = (const float*)d_in[4];
    const float* Wq   = (const float*)d_in[5];
    const float* bq   = (const float*)d_in[6];
    const float* us   = (const float*)d_in[7];
    const float* bsh  = (const float*)d_in[8];
    const float* ul   = (const float*)d_in[9];
    const float* blru = (const float*)d_in[10];
    const float* We   = (const float*)d_in[11];
    const float* be   = (const float*)d_in[12];
    const float* Wch  = (const float*)d_in[13];
    const float* Wci  = (const float*)d_in[14];
    const float* uca  = (const float*)d_in[15];
    const float* bca  = (const float*)d_in[16];

    void* accp = nullptr;
    cudaGetSymbolAddress(&accp, g);
    cudaMemsetAsync(accp, 0, sizeof(Acc));   // zeroes accumulators, zkey(-inf), cnt

    k_matvec<<<1668, 256>>>(h, x, Wq, We, Wch, Wci, us, ul, uca);
    k_pass1<<<1024, 256>>>(amat, mem, ema, bq, bsh, blru);
    k_pass2<<<512, 256>>>(amat, mem, be, bca, (float*)d_out);
}

// round 11
// speedup vs baseline: 1.4468x; 1.2589x over previous
#include <cuda_runtime.h>
#include <math.h>

#define Nn  32768
#define Cc  512
#define Aa  64
#define CIi 1024
#define QD  576          // C + A
#define EPSf 1e-7f

// ---------------- scratch: ONE contiguous struct so a single memset zeroes it ----
struct Acc {
    float q[QD];      // W_query@h partials (bias added later)
    float er[Cc];     // W_erase@h partials
    float t1[Cc];     // Wch@h partials
    float t2[Cc];     // Wci@x partials
    float s1[QD];     // sum_i e_i * full_mem[i,j]
    float s2[Cc];     // sum_i e_i^2 * mem[i,c]
    float scal[16];   // 1:us.h 2:ul.h 3:uca[:N].h 6:uca[N:].x 7:E 8:S
    unsigned zkey;    // order-preserving encoded max; memset-0 == -inf identity
    unsigned cnt;     // last-block-done counter for pass2 finalize
};
__device__ Acc g;
__device__ float g_z[Nn];

__device__ __forceinline__ unsigned encf(float f) {
    unsigned u = __float_as_uint(f);
    return (u & 0x80000000u) ? ~u : (u | 0x80000000u);
}
__device__ __forceinline__ float decf(unsigned k) {
    return __uint_as_float((k & 0x80000000u) ? (k & 0x7FFFFFFFu) : ~k);
}

// ---------------- GEMV helper: 8 rows x 4096-col chunk, atomic partial ----------
__device__ __forceinline__ void gemv8(const float* __restrict__ W, float* out,
                                      int row0, int chunk, const float* __restrict__ h,
                                      int t, int w, int lane)
{
    const float4* v4 = (const float4*)h + chunk * 1024;   // 4096 floats / chunk
    const size_t cbase = (size_t)chunk * 4096;

    float acc[8];
    #pragma unroll
    for (int r = 0; r < 8; r++) acc[r] = 0.f;

    #pragma unroll 2
    for (int i = t; i < 1024; i += 256) {
        float4 hv = v4[i];
        #pragma unroll
        for (int r = 0; r < 8; r++) {
            float4 wv = __ldcs(reinterpret_cast<const float4*>(W + (size_t)(row0 + r) * Nn + cbase) + i);
            acc[r] += wv.x * hv.x + wv.y * hv.y + wv.z * hv.z + wv.w * hv.w;
        }
    }
    #pragma unroll
    for (int r = 0; r < 8; r++)
        for (int o = 16; o; o >>= 1) acc[r] += __shfl_xor_sync(0xffffffffu, acc[r], o);

    __shared__ float sm[8][8];
    if (lane == 0) {
        #pragma unroll
        for (int r = 0; r < 8; r++) sm[w][r] = acc[r];
    }
    __syncthreads();
    if (t < 8) {
        float v = 0.f;
        #pragma unroll
        for (int w2 = 0; w2 < 8; w2++) v += sm[w2][t];
        atomicAdd(&out[row0 + t], v);
    }
}

// ---------------- K1: W_query GEMV + small dots (580 blocks, one wave) -----------
__global__ __launch_bounds__(256) void k_mv_q(
    const float* __restrict__ h,  const float* __restrict__ x,
    const float* __restrict__ Wq,
    const float* __restrict__ us, const float* __restrict__ ul,
    const float* __restrict__ uca)
{
    int b = blockIdx.x, t = threadIdx.x;
    int w = t >> 5, lane = t & 31;

    if (b < 576) {
        gemv8(Wq, g.q, (b >> 3) * 8, b & 7, h, t, w, lane);
    } else {
        int d = b - 576;
        const float* u; const float* vec; int L; int slot;
        if (d == 0)      { u = us;       vec = h; L = Nn;  slot = 1; }
        else if (d == 1) { u = ul;       vec = h; L = Nn;  slot = 2; }
        else if (d == 2) { u = uca;      vec = h; L = Nn;  slot = 3; }
        else             { u = uca + Nn; vec = x; L = CIi; slot = 6; }
        float acc = 0.f;
        const float4* u4 = (const float4*)u;
        const float4* v4 = (const float4*)vec;
        for (int i = t; i < (L >> 2); i += 256) {
            float4 a = u4[i], c = v4[i];
            acc += a.x * c.x + a.y * c.y + a.z * c.z + a.w * c.w;
        }
        for (int o = 16; o; o >>= 1) acc += __shfl_xor_sync(0xffffffffu, acc, o);
        __shared__ float sd[8];
        if (lane == 0) sd[w] = acc;
        __syncthreads();
        if (t == 0) {
            float tot = 0.f;
            #pragma unroll
            for (int k = 0; k < 8; k++) tot += sd[k];
            g.scal[slot] = tot;
        }
    }
}

// ---------------- K2: FUSED rest-matvec (1088 units) + pass1 (1024 units) --------
// Interleaved block mapping keeps both workloads streaming concurrently so the
// wave tail is shared. W loads use __ldcs so pass1's mem/amat stays L2-resident
// for pass2.
//   pass1 unit p: odd b, b < 2048       -> p = b >> 1           (1024 units)
//   rest  unit r: even b -> r = b >> 1; odd b >= 2049 -> r = 1056 + (b-2049)/2
//     r < 512   : We  group r>>3, chunk r&7
//     r < 1024  : Wch group (r-512)>>3, chunk (r-512)&7
//     r < 1088  : Wci group r-1024 (8 rows x 1024, full)
__global__ __launch_bounds__(256) void k_mid(
    const float* __restrict__ h,  const float* __restrict__ x,
    const float* __restrict__ We, const float* __restrict__ Wch,
    const float* __restrict__ Wci,
    const float* __restrict__ Amat, const float* __restrict__ M,
    const float* __restrict__ ema, const float* __restrict__ bq,
    const float* __restrict__ bsh, const float* __restrict__ blru)
{
    int b = blockIdx.x, t = threadIdx.x;
    int w = t >> 5, lane = t & 31;

    bool is_p1 = (b & 1) && (b < 2048);
    if (!is_p1) {
        int r = (b & 1) ? (1056 + ((b - 2049) >> 1)) : (b >> 1);
        if (r < 512) {
            gemv8(We, g.er, (r >> 3) * 8, r & 7, h, t, w, lane);
        } else if (r < 1024) {
            int rr = r - 512;
            gemv8(Wch, g.t1, (rr >> 3) * 8, rr & 7, h, t, w, lane);
        } else {
            // W_ci: 8 rows x 1024, exclusive rows -> plain store
            int row0 = (r - 1024) * 8;
            const float4* v4 = (const float4*)x;
            float acc[8];
            #pragma unroll
            for (int q = 0; q < 8; q++) acc[q] = 0.f;
            {
                int i = t;   // 256 float4 = whole row set
                float4 hv = v4[i];
                #pragma unroll
                for (int q = 0; q < 8; q++) {
                    float4 wv = __ldcs(reinterpret_cast<const float4*>(Wci + (size_t)(row0 + q) * CIi) + i);
                    acc[q] += wv.x * hv.x + wv.y * hv.y + wv.z * hv.z + wv.w * hv.w;
                }
            }
            #pragma unroll
            for (int q = 0; q < 8; q++)
                for (int o = 16; o; o >>= 1) acc[q] += __shfl_xor_sync(0xffffffffu, acc[q], o);
            __shared__ float sm2[8][8];
            if (lane == 0) {
                #pragma unroll
                for (int q = 0; q < 8; q++) sm2[w][q] = acc[q];
            }
            __syncthreads();
            if (t < 8) {
                float v = 0.f;
                #pragma unroll
                for (int w2 = 0; w2 < 8; w2++) v += sm2[w2][t];
                g.t2[row0 + t] = v;
            }
        }
        return;
    }

    // ---- pass1 path ----
    int pb = b >> 1;                  // 0..1023
    __shared__ float qs[QD];
    __shared__ float red[8];
    __shared__ float sc[2];

    float p = 0.f;
    for (int j = t; j < QD; j += 256) {
        float v = g.q[j] + bq[j];
        qs[j] = v;
        p += v * v;
    }
    for (int o = 16; o; o >>= 1) p += __shfl_xor_sync(0xffffffffu, p, o);
    if (lane == 0) red[w] = p;
    __syncthreads();
    if (t == 0) {
        float qs2 = 0.f;
        #pragma unroll
        for (int k = 0; k < 8; k++) qs2 += red[k];
        float qn = fmaxf(sqrtf(qs2), EPSf);
        float bp = g.scal[1] + bsh[0];
        float beta = ((bp > 20.f) ? bp : log1pf(__expf(bp))) + 1.f;
        float gp = g.scal[2] + blru[0];
        sc[0] = beta / qn;
        sc[1] = 1.f / (1.f + __expf(-gp));
    }
    __syncthreads();
    float betap = sc[0], gamma = sc[1];

    int gw = pb * 8 + w;              // 8192 warps, 4 rows each
    float lmax = -3.4e38f;
    #pragma unroll
    for (int rr = 0; rr < 4; rr += 2) {
        int row0 = gw * 4 + rr;
        float2 av0 = ((const float2*)(Amat + (size_t)row0 * Aa))[lane];
        float2 av1 = ((const float2*)(Amat + (size_t)(row0 + 1) * Aa))[lane];
        float q0a = qs[2 * lane], q1a = qs[2 * lane + 1];
        float d0 = av0.x * q0a + av0.y * q1a;
        float s0 = av0.x * av0.x + av0.y * av0.y;
        float d1 = av1.x * q0a + av1.y * q1a;
        float s1 = av1.x * av1.x + av1.y * av1.y;
        const float4* c0 = (const float4*)(M + (size_t)row0 * Cc);
        const float4* c1 = (const float4*)(M + (size_t)(row0 + 1) * Cc);
        #pragma unroll
        for (int k = 0; k < 4; k++) {
            int idx = lane + 32 * k;
            float4 v0 = c0[idx];
            float4 v1 = c1[idx];
            int cb = Aa + 4 * idx;
            float qa = qs[cb], qb2 = qs[cb + 1], qc = qs[cb + 2], qd = qs[cb + 3];
            d0 += v0.x * qa + v0.y * qb2 + v0.z * qc + v0.w * qd;
            s0 += v0.x * v0.x + v0.y * v0.y + v0.z * v0.z + v0.w * v0.w;
            d1 += v1.x * qa + v1.y * qb2 + v1.z * qc + v1.w * qd;
            s1 += v1.x * v1.x + v1.y * v1.y + v1.z * v1.z + v1.w * v1.w;
        }
        #pragma unroll
        for (int o = 16; o; o >>= 1) {
            d0 += __shfl_xor_sync(0xffffffffu, d0, o);
            d1 += __shfl_xor_sync(0xffffffffu, d1, o);
            s0 += __shfl_xor_sync(0xffffffffu, s0, o);
            s1 += __shfl_xor_sync(0xffffffffu, s1, o);
        }
        if (lane == 0) {
            float z0 = betap * d0 / fmaxf(sqrtf(s0), EPSf) - gamma * ema[row0];
            float z1 = betap * d1 / fmaxf(sqrtf(s1), EPSf) - gamma * ema[row0 + 1];
            g_z[row0] = z0;
            g_z[row0 + 1] = z1;
            lmax = fmaxf(lmax, fmaxf(z0, z1));
        }
    }
    if (lane == 0) red[w] = lmax;
    __syncthreads();
    if (t == 0) {
        float m = red[0];
        #pragma unroll
        for (int k = 1; k < 8; k++) m = fmaxf(m, red[k]);
        atomicMax(&g.zkey, encf(m));
    }
}

// ---------------- K3: pass 2 -> s1, s2, E, S; last block writes output -----------
__global__ __launch_bounds__(256) void k_pass2(
    const float* __restrict__ Amat, const float* __restrict__ M,
    const float* __restrict__ be, const float* __restrict__ bca,
    float* __restrict__ out)
{
    __shared__ float s1sh[QD];
    __shared__ float s2sh[Cc];
    __shared__ float es[2];
    __shared__ unsigned lastf;
    int t = threadIdx.x;
    for (int j = t; j < QD; j += 256) s1sh[j] = 0.f;
    for (int j = t; j < Cc; j += 256) s2sh[j] = 0.f;
    if (t == 0) { es[0] = 0.f; es[1] = 0.f; }
    float zmax = decf(g.zkey);
    __syncthreads();

    int w = t >> 5, lane = t & 31;
    int gw = blockIdx.x * 8 + w;                 // 4096 warps, 8 rows each
    float a1x = 0.f, a1y = 0.f;
    float4 c1[4], c2[4];
    #pragma unroll
    for (int k = 0; k < 4; k++) {
        c1[k] = make_float4(0.f, 0.f, 0.f, 0.f);
        c2[k] = make_float4(0.f, 0.f, 0.f, 0.f);
    }
    float eacc = 0.f, sacc = 0.f;

    for (int r = 0; r < 8; r++) {
        int row = gw * 8 + r;
        float e = __expf(g_z[row] - zmax);
        float e2 = e * e;
        float2 av = ((const float2*)(Amat + (size_t)row * Aa))[lane];
        a1x += e * av.x; a1y += e * av.y;
        const float4* c4 = (const float4*)(M + (size_t)row * Cc);
        #pragma unroll
        for (int k = 0; k < 4; k++) {
            float4 v = c4[lane + 32 * k];
            c1[k].x += e * v.x;  c1[k].y += e * v.y;  c1[k].z += e * v.z;  c1[k].w += e * v.w;
            c2[k].x += e2 * v.x; c2[k].y += e2 * v.y; c2[k].z += e2 * v.z; c2[k].w += e2 * v.w;
        }
        if (lane == 0) { eacc += e; sacc += e2; }
    }

    atomicAdd(&s1sh[2 * lane],     a1x);
    atomicAdd(&s1sh[2 * lane + 1], a1y);
    #pragma unroll
    for (int k = 0; k < 4; k++) {
        int base = 4 * (lane + 32 * k);
        atomicAdd(&s1sh[Aa + base + 0], c1[k].x);
        atomicAdd(&s1sh[Aa + base + 1], c1[k].y);
        atomicAdd(&s1sh[Aa + base + 2], c1[k].z);
        atomicAdd(&s1sh[Aa + base + 3], c1[k].w);
        atomicAdd(&s2sh[base + 0], c2[k].x);
        atomicAdd(&s2sh[base + 1], c2[k].y);
        atomicAdd(&s2sh[base + 2], c2[k].z);
        atomicAdd(&s2sh[base + 3], c2[k].w);
    }
    if (lane == 0) { atomicAdd(&es[0], eacc); atomicAdd(&es[1], sacc); }
    __syncthreads();

    for (int j = t; j < QD; j += 256) atomicAdd(&g.s1[j], s1sh[j]);
    for (int j = t; j < Cc; j += 256) atomicAdd(&g.s2[j], s2sh[j]);
    if (t == 0) { atomicAdd(&g.scal[7], es[0]); atomicAdd(&g.scal[8], es[1]); }

    // last-block-done: final combine + output write
    __threadfence();
    if (t == 0) {
        unsigned old = atomicAdd(&g.cnt, 1u);
        lastf = (old == gridDim.x - 1) ? 1u : 0u;
    }
    __syncthreads();
    if (lastf) {
        __threadfence();
        float E = __ldcg(&g.scal[7]);
        float S = __ldcg(&g.scal[8]);
        float invE = 1.f / E;
        float inv2 = invE * invE;
        float alpha = g.scal[3] + g.scal[6] + bca[0];
        for (int j = t; j < QD; j += 256) {
            float s1v = __ldcg(&g.s1[j]);
            if (j < Aa) {
                out[j] = s1v * invE;
            } else {
                int c = j - Aa;
                float cand = fmaxf(g.t1[c] + alpha * g.t2[c], 0.f);
                float erv  = g.er[c] + be[c];
                out[j] = s1v * invE - erv * (__ldcg(&g.s2[c]) * inv2) + cand * (S * inv2);
            }
        }
    }
}

extern "C" void kernel_launch(void* const* d_in, const int* in_sizes, int n_in,
                              void* d_out, int out_size)
{
    const float* h    = (const float*)d_in[0];
    const float* x    = (const float*)d_in[1];
    const float* mem  = (const float*)d_in[2];
    const float* amat = (const float*)d_in[3];
    const float* ema  = (const float*)d_in[4];
    const float* Wq   = (const float*)d_in[5];
    const float* bq   = (const float*)d_in[6];
    const float* us   = (const float*)d_in[7];
    const float* bsh  = (const float*)d_in[8];
    const float* ul   = (const float*)d_in[9];
    const float* blru = (const float*)d_in[10];
    const float* We   = (const float*)d_in[11];
    const float* be   = (const float*)d_in[12];
    const float* Wch  = (const float*)d_in[13];
    const float* Wci  = (const float*)d_in[14];
    const float* uca  = (const float*)d_in[15];
    const float* bca  = (const float*)d_in[16];

    void* accp = nullptr;
    cudaGetSymbolAddress(&accp, g);
    cudaMemsetAsync(accp, 0, sizeof(Acc));   // zeroes accumulators, zkey(-inf), cnt

    k_mv_q<<<580, 256>>>(h, x, Wq, us, ul, uca);
    k_mid<<<2112, 256>>>(h, x, We, Wch, Wci, amat, mem, ema, bq, bsh, blru);
    k_pass2<<<512, 256>>>(amat, mem, be, bca, (float*)d_out);
}